// round 14
// baseline (speedup 1.0000x reference)
#include <cuda_runtime.h>
#include <cstdint>

#define HH 128
#define WW 128
#define HWSZ (HH * WW)

#define GSPLIT 4   // deform group-split factor

// ---------------- scratch (zero-initialized device globals) ----------------
__device__ float  g_h1 [2 * 64 * HWSZ];
__device__ float  g_h2 [2 * 64 * HWSZ];
__device__ float  g_o  [2 * 432 * HWSZ];
__device__ float4 g_xt [2 * 16 * HWSZ];
__device__ float  g_part[2 * GSPLIT * 64 * HWSZ];

// ---------------- cp.async helpers ----------------
__device__ __forceinline__ unsigned su32(const void* p) {
    return (unsigned)__cvta_generic_to_shared(p);
}
__device__ __forceinline__ void cpa16(unsigned d, const void* s) {
    asm volatile("cp.async.ca.shared.global [%0], [%1], 16;" :: "r"(d), "l"(s));
}
__device__ __forceinline__ void cpa4(unsigned d, const void* s) {
    asm volatile("cp.async.ca.shared.global [%0], [%1], 4;" :: "r"(d), "l"(s));
}
__device__ __forceinline__ void cpcommit() { asm volatile("cp.async.commit_group;"); }
__device__ __forceinline__ void cpwait0()  { asm volatile("cp.async.wait_group 0;"); }
__device__ __forceinline__ void cpwait1()  { asm volatile("cp.async.wait_group 1;"); }

// ---------------- conv 3x3 fp32, raw-layout staging, cp.async double-buffered ----------
// tile 32x32, 256 threads, 2x2 px/thread, OCB=8, CCHUNK=4, 3 CTAs/SM target.
constexpr int CCH = 4;
constexpr int SIN_BUF = CCH * 34 * 40;            // 5440 floats per buffer
constexpr int SW_BUF  = 8 * CCH * 9;              // 288 floats
constexpr int SMEM_CONV = (2 * SIN_BUF + 2 * SW_BUF) * 4;

template <bool LEAKY>
__global__ __launch_bounds__(256, 3)
void conv3x3_kernel(const float* __restrict__ in,    // raw [B*Cin, 128, 128]
                    const float* __restrict__ wgt,
                    const float* __restrict__ bias,
                    float* __restrict__ out,          // raw [B*Cout, 128, 128]
                    int Cin, int Cout) {
    extern __shared__ float smem[];
    float* s_in = smem;                 // [2][CCH][34][40]
    float* s_w  = smem + 2 * SIN_BUF;   // [2][8 oc][CCH ci][9]

    const int tid = threadIdx.x;
    const int tx = tid & 15;
    const int ty = tid >> 4;
    const int tile = blockIdx.x;
    const int y0 = (tile >> 2) * 32;
    const int x0 = (tile & 3) * 32;
    const int ocb = blockIdx.y;
    const int b = blockIdx.z;

    const float* in_b = in + (size_t)b * Cin * HWSZ;
    const int s_ch = tid >> 6;       // 0..3
    const int s_ln = tid & 63;       // 0..63

    // zero both input buffers once: OOB slots stay zero for the whole kernel
    for (int i = tid; i < 2 * SIN_BUF; i += 256) s_in[i] = 0.f;
    __syncthreads();

    float acc[8][4];
#pragma unroll
    for (int i = 0; i < 8; i++) {
        acc[i][0] = 0.f; acc[i][1] = 0.f; acc[i][2] = 0.f; acc[i][3] = 0.f;
    }

    // chunk q (0..9) covers gx = x0-4+4q .. x0-1+4q; fully OOB iff (q==0 && x0==0)
    // or (q==9 && x0==96). row r: gy = y0-1+r, OOB iff gy<0 || gy>127.
    const int qlo = (x0 == 0) ? 1 : 0;
    const int qhi = (x0 == 96) ? 9 : 10;

    auto stage = [&](int c0, int bufi) {
        const float* src = in_b + (size_t)(c0 + s_ch) * HWSZ + (y0 - 1) * WW + x0 - 4;
        float* dst = s_in + (bufi * CCH + s_ch) * (34 * 40);
        for (int idx = s_ln; idx < 340; idx += 64) {
            int r = idx / 10;
            int q = idx - r * 10;
            int gy = y0 - 1 + r;
            if (((unsigned)gy < HH) && q >= qlo && q < qhi)
                cpa16(su32(dst + r * 40 + q * 4), src + r * WW + q * 4);
        }
        for (int idx = tid; idx < 8 * CCH * 9; idx += 256) {
            int oc = idx / (CCH * 9);
            int rem = idx - oc * (CCH * 9);
            int ci = rem / 9;
            int k = rem - ci * 9;
            cpa4(su32(s_w + bufi * SW_BUF + (oc * CCH + ci) * 9 + k),
                 wgt + ((size_t)(ocb * 8 + oc) * Cin + c0 + ci) * 9 + k);
        }
    };

    stage(0, 0);
    cpcommit();

    int buf = 0;
    for (int c0 = 0; c0 < Cin; c0 += CCH) {
        if (c0 + CCH < Cin) {
            stage(c0 + CCH, buf ^ 1);
            cpcommit();
            cpwait1();
        } else {
            cpwait0();
        }
        __syncthreads();

        const float* si = s_in + buf * SIN_BUF;
        const float* sw = s_w + buf * SW_BUF;
#pragma unroll
        for (int ci = 0; ci < CCH; ci++) {
            const float* sc = si + ci * (34 * 40);
            float iv[4][4];
#pragma unroll
            for (int dy = 0; dy < 4; dy++)
#pragma unroll
                for (int dx = 0; dx < 4; dx++)
                    iv[dy][dx] = sc[(2 * ty + dy) * 40 + 2 * tx + dx + 3];
#pragma unroll
            for (int oc = 0; oc < 8; oc++) {
#pragma unroll
                for (int ky = 0; ky < 3; ky++)
#pragma unroll
                    for (int kx = 0; kx < 3; kx++) {
                        float w = sw[(oc * CCH + ci) * 9 + ky * 3 + kx];
                        acc[oc][0] = fmaf(iv[ky][kx],         w, acc[oc][0]);
                        acc[oc][1] = fmaf(iv[ky][kx + 1],     w, acc[oc][1]);
                        acc[oc][2] = fmaf(iv[ky + 1][kx],     w, acc[oc][2]);
                        acc[oc][3] = fmaf(iv[ky + 1][kx + 1], w, acc[oc][3]);
                    }
            }
        }
        __syncthreads();
        buf ^= 1;
    }

    const int oy = y0 + 2 * ty;
    const int ox = x0 + 2 * tx;
#pragma unroll
    for (int oc = 0; oc < 8; oc++) {
        float bv = bias[ocb * 8 + oc];
        float* op = out + (size_t)(b * Cout + ocb * 8 + oc) * HWSZ;
#pragma unroll
        for (int q = 0; q < 4; q++) {
            float v = acc[oc][q] + bv;
            if (LEAKY) v = (v >= 0.f) ? v : 0.1f * v;
            int yy = oy + (q >> 1);
            int xx = ox + (q & 1);
            op[yy * WW + xx] = v;
        }
    }
}

// ---------------- x transpose: [B,64,H,W] -> [B,16,H,W,4] ----------------
__global__ void transpose_x_kernel(const float* __restrict__ x, float4* __restrict__ xt) {
    int idx = blockIdx.x * 256 + threadIdx.x;
    if (idx >= 2 * 16 * HWSZ) return;
    int p = idx & (HWSZ - 1);
    int bg = idx / HWSZ;
    const float* src = x + (size_t)bg * 4 * HWSZ + p;
    float4 v;
    v.x = src[0];
    v.y = src[HWSZ];
    v.z = src[2 * HWSZ];
    v.w = src[3 * HWSZ];
    xt[idx] = v;
}

// ---------------- deformable gather + block GEMM, group-split partials [R11 winner] ----
__global__ __launch_bounds__(128, 3)
void deform_kernel(const float4* __restrict__ xt,
                   const float* __restrict__ o,
                   const float* __restrict__ flow,
                   const float* __restrict__ weight,   // [64][576]
                   float* __restrict__ part) {
    __shared__ __align__(16) float s_w[36 * 64];
    __shared__ __align__(16) float s_val[36 * 128];

    const int tid = threadIdx.x;
    const int b = blockIdx.z;
    const int gbase = blockIdx.y * (16 / GSPLIT);
    const int p0 = blockIdx.x * 128;
    const int p = p0 + tid;
    const int h = p >> 7;
    const int w = p & 127;
    const int px0 = (tid & 15) * 8;
    const int oc0 = (tid >> 4) * 8;

    const float* ob = o + (size_t)b * 432 * HWSZ + p;
    const float fy = flow[((size_t)b * 2 + 1) * HWSZ + p];
    const float fx = flow[((size_t)b * 2 + 0) * HWSZ + p];

    float acc[8][8];
#pragma unroll
    for (int i = 0; i < 8; i++)
#pragma unroll
        for (int j = 0; j < 8; j++) acc[i][j] = 0.f;

    for (int gi = 0; gi < 16 / GSPLIT; gi++) {
        const int g = gbase + gi;
        for (int idx = tid; idx < 36 * 64; idx += 128) {
            int m = idx >> 6;
            int oo = idx & 63;
            cpa4(su32(s_w + idx), weight + (size_t)oo * 576 + g * 36 + m);
        }
        cpcommit();

        const float4* xg = xt + (size_t)(b * 16 + g) * HWSZ;
#pragma unroll
        for (int k = 0; k < 9; k++) {
            float lo_y = ob[(size_t)(g * 18 + 2 * k) * HWSZ];
            float lo_x = ob[(size_t)(g * 18 + 2 * k + 1) * HWSZ];
            float lo_m = ob[(size_t)(288 + g * 9 + k) * HWSZ];

            float offy = 10.f * tanhf(lo_y) + fy;
            float offx = 10.f * tanhf(lo_x) + fx;
            float msk = 1.f / (1.f + expf(-lo_m));

            float py = (float)(h + (k / 3) - 1) + offy;
            float px = (float)(w + (k % 3) - 1) + offx;

            float y0f = floorf(py);
            float x0f = floorf(px);
            float wy = py - y0f;
            float wx = px - x0f;
            int y0 = (int)y0f;
            int x0 = (int)x0f;

            bool y0v = ((unsigned)y0 < HH);
            bool y1v = ((unsigned)(y0 + 1) < HH);
            bool x0v = ((unsigned)x0 < WW);
            bool x1v = ((unsigned)(x0 + 1) < WW);

            float4 v00 = make_float4(0.f, 0.f, 0.f, 0.f);
            float4 v01 = v00, v10 = v00, v11 = v00;
            if (y0v && x0v) v00 = __ldg(&xg[y0 * WW + x0]);
            if (y0v && x1v) v01 = __ldg(&xg[y0 * WW + x0 + 1]);
            if (y1v && x0v) v10 = __ldg(&xg[(y0 + 1) * WW + x0]);
            if (y1v && x1v) v11 = __ldg(&xg[(y0 + 1) * WW + x0 + 1]);

            float w00 = (1.f - wy) * (1.f - wx);
            float w01 = (1.f - wy) * wx;
            float w10 = wy * (1.f - wx);
            float w11 = wy * wx;

            s_val[(0 * 9 + k) * 128 + tid] = msk * (w00 * v00.x + w01 * v01.x + w10 * v10.x + w11 * v11.x);
            s_val[(1 * 9 + k) * 128 + tid] = msk * (w00 * v00.y + w01 * v01.y + w10 * v10.y + w11 * v11.y);
            s_val[(2 * 9 + k) * 128 + tid] = msk * (w00 * v00.z + w01 * v01.z + w10 * v10.z + w11 * v11.z);
            s_val[(3 * 9 + k) * 128 + tid] = msk * (w00 * v00.w + w01 * v01.w + w10 * v10.w + w11 * v11.w);
        }

        cpwait0();
        __syncthreads();

#pragma unroll
        for (int m = 0; m < 36; m++) {
            float4 wa = *(const float4*)(s_w + m * 64 + oc0);
            float4 wb = *(const float4*)(s_w + m * 64 + oc0 + 4);
            float4 va = *(const float4*)(s_val + m * 128 + px0);
            float4 vb = *(const float4*)(s_val + m * 128 + px0 + 4);
            float wv[8] = { wa.x, wa.y, wa.z, wa.w, wb.x, wb.y, wb.z, wb.w };
            float vv[8] = { va.x, va.y, va.z, va.w, vb.x, vb.y, vb.z, vb.w };
#pragma unroll
            for (int i = 0; i < 8; i++)
#pragma unroll
                for (int j = 0; j < 8; j++)
                    acc[i][j] = fmaf(wv[i], vv[j], acc[i][j]);
        }
        __syncthreads();
    }

    float* pb = part + ((size_t)(b * GSPLIT + blockIdx.y) * 64) * HWSZ;
#pragma unroll
    for (int i = 0; i < 8; i++) {
        float* op = pb + (size_t)(oc0 + i) * HWSZ + p0 + px0;
        *(float4*)op       = make_float4(acc[i][0], acc[i][1], acc[i][2], acc[i][3]);
        *(float4*)(op + 4) = make_float4(acc[i][4], acc[i][5], acc[i][6], acc[i][7]);
    }
}

// ---------------- partial reduction ----------------
__global__ void reduce_kernel(const float4* __restrict__ part, float4* __restrict__ out) {
    int idx = blockIdx.x * 256 + threadIdx.x;
    if (idx >= 2 * 64 * HWSZ / 4) return;
    int b = idx / (64 * HWSZ / 4);
    int r = idx - b * (64 * HWSZ / 4);
    const float4* pp = part + (size_t)b * GSPLIT * (64 * HWSZ / 4) + r;
    float4 s = pp[0];
#pragma unroll
    for (int k = 1; k < GSPLIT; k++) {
        float4 v = pp[(size_t)k * (64 * HWSZ / 4)];
        s.x += v.x; s.y += v.y; s.z += v.z; s.w += v.w;
    }
    out[idx] = s;
}

// ---------------- launch ----------------
extern "C" void kernel_launch(void* const* d_in, const int* in_sizes, int n_in,
                              void* d_out, int out_size) {
    const float* x          = (const float*)d_in[0];
    const float* extra_feat = (const float*)d_in[1];
    const float* flow       = (const float*)d_in[2];
    const float* w1         = (const float*)d_in[3];
    const float* b1         = (const float*)d_in[4];
    const float* w2         = (const float*)d_in[5];
    const float* b2         = (const float*)d_in[6];
    const float* w3         = (const float*)d_in[7];
    const float* b3         = (const float*)d_in[8];
    const float* weight     = (const float*)d_in[9];
    float* out = (float*)d_out;

    float *h1, *h2, *obuf, *partb;
    float4* xt;
    cudaGetSymbolAddress((void**)&h1, g_h1);
    cudaGetSymbolAddress((void**)&h2, g_h2);
    cudaGetSymbolAddress((void**)&obuf, g_o);
    cudaGetSymbolAddress((void**)&xt, g_xt);
    cudaGetSymbolAddress((void**)&partb, g_part);

    cudaFuncSetAttribute(conv3x3_kernel<true>,
                         cudaFuncAttributeMaxDynamicSharedMemorySize, SMEM_CONV);
    cudaFuncSetAttribute(conv3x3_kernel<false>,
                         cudaFuncAttributeMaxDynamicSharedMemorySize, SMEM_CONV);

    transpose_x_kernel<<<(2 * 16 * HWSZ + 255) / 256, 256>>>(x, xt);

    // conv1: 128 -> 64, leaky (reads raw extra_feat)
    conv3x3_kernel<true><<<dim3(16, 8, 2), 256, SMEM_CONV>>>(extra_feat, w1, b1, h1, 128, 64);
    // conv2: 64 -> 64, leaky
    conv3x3_kernel<true><<<dim3(16, 8, 2), 256, SMEM_CONV>>>(h1, w2, b2, h2, 64, 64);
    // conv3: 64 -> 432, linear
    conv3x3_kernel<false><<<dim3(16, 54, 2), 256, SMEM_CONV>>>(h2, w3, b3, obuf, 64, 432);

    deform_kernel<<<dim3(HWSZ / 128, GSPLIT, 2), 128>>>(xt, obuf, flow, weight, partb);
    reduce_kernel<<<(2 * 64 * HWSZ / 4 + 255) / 256, 256>>>((const float4*)partb, (float4*)out);
}

// round 15
// speedup vs baseline: 1.0076x; 1.0076x over previous
#include <cuda_runtime.h>
#include <cstdint>

#define HH 128
#define WW 128
#define HWSZ (HH * WW)

// padded geometry for conv1/conv2 inputs: 130 x 136, interior (y,x) -> (y+1)*136+(x+4)
#define PW 136
#define PH 130
#define PHW (PH * PW)

#define GSPLIT 4

// ---------------- scratch (zero-initialized device globals; halo never written) -------
__device__ float  g_efp[2 * 128 * PHW];          // padded extra_feat
__device__ float  g_h1p[2 * 64 * PHW];           // padded conv1 out
__device__ float  g_h2 [2 * 64 * HWSZ];          // raw conv2 out
__device__ float  g_o  [2 * 432 * HWSZ];
__device__ float4 g_xt [2 * 16 * HWSZ];
__device__ float  g_part[2 * GSPLIT * 64 * HWSZ];

// ---------------- cp.async helpers ----------------
__device__ __forceinline__ unsigned su32(const void* p) {
    return (unsigned)__cvta_generic_to_shared(p);
}
__device__ __forceinline__ void cpa16(unsigned d, const void* s) {
    asm volatile("cp.async.ca.shared.global [%0], [%1], 16;" :: "r"(d), "l"(s));
}
__device__ __forceinline__ void cpa4(unsigned d, const void* s) {
    asm volatile("cp.async.ca.shared.global [%0], [%1], 4;" :: "r"(d), "l"(s));
}
__device__ __forceinline__ void cpcommit() { asm volatile("cp.async.commit_group;"); }
__device__ __forceinline__ void cpwait0()  { asm volatile("cp.async.wait_group 0;"); }
__device__ __forceinline__ void cpwait1()  { asm volatile("cp.async.wait_group 1;"); }

// ---------------- pad copy: [BC,128,128] -> padded [BC,130,136] interior --------------
__global__ void pad_kernel(const float* __restrict__ in, float* __restrict__ outp, int n) {
    int idx = blockIdx.x * 256 + threadIdx.x;
    if (idx >= n) return;
    int p = idx & (HWSZ - 1);
    int bc = idx >> 14;
    int y = p >> 7;
    int x = p & 127;
    outp[(size_t)bc * PHW + (y + 1) * PW + x + 4] = in[idx];
}

// ============ conv variant A: padded input, CCHUNK=8, 2 CTA/SM (R10/R11 winner) =======
constexpr int SIN8 = 8 * 34 * 40;
constexpr int SW8  = 8 * 8 * 9;
constexpr int SMEM_PAD = (2 * SIN8 + 2 * SW8) * 4;

template <bool LEAKY>
__global__ __launch_bounds__(256, 2)
void conv_pad_kernel(const float* __restrict__ in,    // padded [B*Cin, PH, PW]
                     const float* __restrict__ wgt,
                     const float* __restrict__ bias,
                     float* __restrict__ out,
                     int Cin, int Cout, int OS, int OB, size_t ocs) {
    extern __shared__ float smem[];
    float* s_in = smem;
    float* s_w  = smem + 2 * SIN8;

    const int tid = threadIdx.x;
    const int tx = tid & 15;
    const int ty = tid >> 4;
    const int tile = blockIdx.x;
    const int y0 = (tile >> 2) * 32;
    const int x0 = (tile & 3) * 32;
    const int ocb = blockIdx.y;
    const int b = blockIdx.z;

    const float* in_b = in + (size_t)b * Cin * PHW;
    const int s_ch = tid >> 5;
    const int s_ln = tid & 31;

    float acc[8][4];
#pragma unroll
    for (int i = 0; i < 8; i++) {
        acc[i][0] = 0.f; acc[i][1] = 0.f; acc[i][2] = 0.f; acc[i][3] = 0.f;
    }

    auto stage = [&](int c0, int bufi) {
        const float* src = in_b + (size_t)(c0 + s_ch) * PHW + y0 * PW + x0;
        float* dst = s_in + (size_t)(bufi * 8 + s_ch) * (34 * 40);
        for (int idx = s_ln; idx < 340; idx += 32) {
            int r = idx / 10;
            int q = idx - r * 10;
            cpa16(su32(dst + r * 40 + q * 4), src + r * PW + q * 4);
        }
        for (int idx = tid; idx < 576; idx += 256) {
            int oc = idx / 72;
            int rem = idx - oc * 72;
            int ci = rem / 9;
            int k = rem - ci * 9;
            cpa4(su32(s_w + bufi * SW8 + (oc * 8 + ci) * 9 + k),
                 wgt + ((size_t)(ocb * 8 + oc) * Cin + c0 + ci) * 9 + k);
        }
    };

    stage(0, 0);
    cpcommit();

    int buf = 0;
    for (int c0 = 0; c0 < Cin; c0 += 8) {
        if (c0 + 8 < Cin) {
            stage(c0 + 8, buf ^ 1);
            cpcommit();
            cpwait1();
        } else {
            cpwait0();
        }
        __syncthreads();

        const float* si = s_in + buf * SIN8;
        const float* sw = s_w + buf * SW8;
#pragma unroll
        for (int ci = 0; ci < 8; ci++) {
            const float* sc = si + ci * (34 * 40);
            float iv[4][4];
#pragma unroll
            for (int dy = 0; dy < 4; dy++)
#pragma unroll
                for (int dx = 0; dx < 4; dx++)
                    iv[dy][dx] = sc[(2 * ty + dy) * 40 + 2 * tx + dx + 3];
#pragma unroll
            for (int oc = 0; oc < 8; oc++) {
#pragma unroll
                for (int ky = 0; ky < 3; ky++)
#pragma unroll
                    for (int kx = 0; kx < 3; kx++) {
                        float w = sw[(oc * 8 + ci) * 9 + ky * 3 + kx];
                        acc[oc][0] = fmaf(iv[ky][kx],         w, acc[oc][0]);
                        acc[oc][1] = fmaf(iv[ky][kx + 1],     w, acc[oc][1]);
                        acc[oc][2] = fmaf(iv[ky + 1][kx],     w, acc[oc][2]);
                        acc[oc][3] = fmaf(iv[ky + 1][kx + 1], w, acc[oc][3]);
                    }
            }
        }
        __syncthreads();
        buf ^= 1;
    }

    const int oy = y0 + 2 * ty;
    const int ox = x0 + 2 * tx;
#pragma unroll
    for (int oc = 0; oc < 8; oc++) {
        float bv = bias[ocb * 8 + oc];
        float* op = out + (size_t)(b * Cout + ocb * 8 + oc) * ocs + OB;
#pragma unroll
        for (int q = 0; q < 4; q++) {
            float v = acc[oc][q] + bv;
            if (LEAKY) v = (v >= 0.f) ? v : 0.1f * v;
            int yy = oy + (q >> 1);
            int xx = ox + (q & 1);
            op[yy * OS + xx] = v;
        }
    }
}

// ============ conv variant B: raw input, CCHUNK=4, 3 CTA/SM (R12, best for conv3) =====
constexpr int CCH = 4;
constexpr int SIN4 = CCH * 34 * 40;
constexpr int SW4  = 8 * CCH * 9;
constexpr int SMEM_RAW = (2 * SIN4 + 2 * SW4) * 4;

template <bool LEAKY>
__global__ __launch_bounds__(256, 3)
void conv_raw_kernel(const float* __restrict__ in,    // raw [B*Cin, 128, 128]
                     const float* __restrict__ wgt,
                     const float* __restrict__ bias,
                     float* __restrict__ out,
                     int Cin, int Cout) {
    extern __shared__ float smem[];
    float* s_in = smem;
    float* s_w  = smem + 2 * SIN4;

    const int tid = threadIdx.x;
    const int tx = tid & 15;
    const int ty = tid >> 4;
    const int tile = blockIdx.x;
    const int y0 = (tile >> 2) * 32;
    const int x0 = (tile & 3) * 32;
    const int ocb = blockIdx.y;
    const int b = blockIdx.z;

    const float* in_b = in + (size_t)b * Cin * HWSZ;
    const int s_ch = tid >> 6;
    const int s_ln = tid & 63;

    for (int i = tid; i < 2 * SIN4; i += 256) s_in[i] = 0.f;
    __syncthreads();

    float acc[8][4];
#pragma unroll
    for (int i = 0; i < 8; i++) {
        acc[i][0] = 0.f; acc[i][1] = 0.f; acc[i][2] = 0.f; acc[i][3] = 0.f;
    }

    const int qlo = (x0 == 0) ? 1 : 0;
    const int qhi = (x0 == 96) ? 9 : 10;

    auto stage = [&](int c0, int bufi) {
        const float* src = in_b + (size_t)(c0 + s_ch) * HWSZ + (y0 - 1) * WW + x0 - 4;
        float* dst = s_in + (bufi * CCH + s_ch) * (34 * 40);
        for (int idx = s_ln; idx < 340; idx += 64) {
            int r = idx / 10;
            int q = idx - r * 10;
            int gy = y0 - 1 + r;
            if (((unsigned)gy < HH) && q >= qlo && q < qhi)
                cpa16(su32(dst + r * 40 + q * 4), src + r * WW + q * 4);
        }
        for (int idx = tid; idx < 8 * CCH * 9; idx += 256) {
            int oc = idx / (CCH * 9);
            int rem = idx - oc * (CCH * 9);
            int ci = rem / 9;
            int k = rem - ci * 9;
            cpa4(su32(s_w + bufi * SW4 + (oc * CCH + ci) * 9 + k),
                 wgt + ((size_t)(ocb * 8 + oc) * Cin + c0 + ci) * 9 + k);
        }
    };

    stage(0, 0);
    cpcommit();

    int buf = 0;
    for (int c0 = 0; c0 < Cin; c0 += CCH) {
        if (c0 + CCH < Cin) {
            stage(c0 + CCH, buf ^ 1);
            cpcommit();
            cpwait1();
        } else {
            cpwait0();
        }
        __syncthreads();

        const float* si = s_in + buf * SIN4;
        const float* sw = s_w + buf * SW4;
#pragma unroll
        for (int ci = 0; ci < CCH; ci++) {
            const float* sc = si + ci * (34 * 40);
            float iv[4][4];
#pragma unroll
            for (int dy = 0; dy < 4; dy++)
#pragma unroll
                for (int dx = 0; dx < 4; dx++)
                    iv[dy][dx] = sc[(2 * ty + dy) * 40 + 2 * tx + dx + 3];
#pragma unroll
            for (int oc = 0; oc < 8; oc++) {
#pragma unroll
                for (int ky = 0; ky < 3; ky++)
#pragma unroll
                    for (int kx = 0; kx < 3; kx++) {
                        float w = sw[(oc * CCH + ci) * 9 + ky * 3 + kx];
                        acc[oc][0] = fmaf(iv[ky][kx],         w, acc[oc][0]);
                        acc[oc][1] = fmaf(iv[ky][kx + 1],     w, acc[oc][1]);
                        acc[oc][2] = fmaf(iv[ky + 1][kx],     w, acc[oc][2]);
                        acc[oc][3] = fmaf(iv[ky + 1][kx + 1], w, acc[oc][3]);
                    }
            }
        }
        __syncthreads();
        buf ^= 1;
    }

    const int oy = y0 + 2 * ty;
    const int ox = x0 + 2 * tx;
#pragma unroll
    for (int oc = 0; oc < 8; oc++) {
        float bv = bias[ocb * 8 + oc];
        float* op = out + (size_t)(b * Cout + ocb * 8 + oc) * HWSZ;
#pragma unroll
        for (int q = 0; q < 4; q++) {
            float v = acc[oc][q] + bv;
            if (LEAKY) v = (v >= 0.f) ? v : 0.1f * v;
            int yy = oy + (q >> 1);
            int xx = ox + (q & 1);
            op[yy * WW + xx] = v;
        }
    }
}

// ---------------- x transpose: [B,64,H,W] -> [B,16,H,W,4] ----------------
__global__ void transpose_x_kernel(const float* __restrict__ x, float4* __restrict__ xt) {
    int idx = blockIdx.x * 256 + threadIdx.x;
    if (idx >= 2 * 16 * HWSZ) return;
    int p = idx & (HWSZ - 1);
    int bg = idx / HWSZ;
    const float* src = x + (size_t)bg * 4 * HWSZ + p;
    float4 v;
    v.x = src[0];
    v.y = src[HWSZ];
    v.z = src[2 * HWSZ];
    v.w = src[3 * HWSZ];
    xt[idx] = v;
}

// ---------------- deformable gather + block GEMM, group-split partials ----------------
__global__ __launch_bounds__(128, 3)
void deform_kernel(const float4* __restrict__ xt,
                   const float* __restrict__ o,
                   const float* __restrict__ flow,
                   const float* __restrict__ weight,   // [64][576]
                   float* __restrict__ part) {
    __shared__ __align__(16) float s_w[36 * 64];
    __shared__ __align__(16) float s_val[36 * 128];

    const int tid = threadIdx.x;
    const int b = blockIdx.z;
    const int gbase = blockIdx.y * (16 / GSPLIT);
    const int p0 = blockIdx.x * 128;
    const int p = p0 + tid;
    const int h = p >> 7;
    const int w = p & 127;
    const int px0 = (tid & 15) * 8;
    const int oc0 = (tid >> 4) * 8;

    const float* ob = o + (size_t)b * 432 * HWSZ + p;
    const float fy = flow[((size_t)b * 2 + 1) * HWSZ + p];
    const float fx = flow[((size_t)b * 2 + 0) * HWSZ + p];

    float acc[8][8];
#pragma unroll
    for (int i = 0; i < 8; i++)
#pragma unroll
        for (int j = 0; j < 8; j++) acc[i][j] = 0.f;

    for (int gi = 0; gi < 16 / GSPLIT; gi++) {
        const int g = gbase + gi;
        for (int idx = tid; idx < 36 * 64; idx += 128) {
            int m = idx >> 6;
            int oo = idx & 63;
            cpa4(su32(s_w + idx), weight + (size_t)oo * 576 + g * 36 + m);
        }
        cpcommit();

        const float4* xg = xt + (size_t)(b * 16 + g) * HWSZ;
#pragma unroll
        for (int k = 0; k < 9; k++) {
            float lo_y = ob[(size_t)(g * 18 + 2 * k) * HWSZ];
            float lo_x = ob[(size_t)(g * 18 + 2 * k + 1) * HWSZ];
            float lo_m = ob[(size_t)(288 + g * 9 + k) * HWSZ];

            float offy = 10.f * tanhf(lo_y) + fy;
            float offx = 10.f * tanhf(lo_x) + fx;
            float msk = 1.f / (1.f + expf(-lo_m));

            float py = (float)(h + (k / 3) - 1) + offy;
            float px = (float)(w + (k % 3) - 1) + offx;

            float y0f = floorf(py);
            float x0f = floorf(px);
            float wy = py - y0f;
            float wx = px - x0f;
            int y0 = (int)y0f;
            int x0 = (int)x0f;

            bool y0v = ((unsigned)y0 < HH);
            bool y1v = ((unsigned)(y0 + 1) < HH);
            bool x0v = ((unsigned)x0 < WW);
            bool x1v = ((unsigned)(x0 + 1) < WW);

            float4 v00 = make_float4(0.f, 0.f, 0.f, 0.f);
            float4 v01 = v00, v10 = v00, v11 = v00;
            if (y0v && x0v) v00 = __ldg(&xg[y0 * WW + x0]);
            if (y0v && x1v) v01 = __ldg(&xg[y0 * WW + x0 + 1]);
            if (y1v && x0v) v10 = __ldg(&xg[(y0 + 1) * WW + x0]);
            if (y1v && x1v) v11 = __ldg(&xg[(y0 + 1) * WW + x0 + 1]);

            float w00 = (1.f - wy) * (1.f - wx);
            float w01 = (1.f - wy) * wx;
            float w10 = wy * (1.f - wx);
            float w11 = wy * wx;

            s_val[(0 * 9 + k) * 128 + tid] = msk * (w00 * v00.x + w01 * v01.x + w10 * v10.x + w11 * v11.x);
            s_val[(1 * 9 + k) * 128 + tid] = msk * (w00 * v00.y + w01 * v01.y + w10 * v10.y + w11 * v11.y);
            s_val[(2 * 9 + k) * 128 + tid] = msk * (w00 * v00.z + w01 * v01.z + w10 * v10.z + w11 * v11.z);
            s_val[(3 * 9 + k) * 128 + tid] = msk * (w00 * v00.w + w01 * v01.w + w10 * v10.w + w11 * v11.w);
        }

        cpwait0();
        __syncthreads();

#pragma unroll
        for (int m = 0; m < 36; m++) {
            float4 wa = *(const float4*)(s_w + m * 64 + oc0);
            float4 wb = *(const float4*)(s_w + m * 64 + oc0 + 4);
            float4 va = *(const float4*)(s_val + m * 128 + px0);
            float4 vb = *(const float4*)(s_val + m * 128 + px0 + 4);
            float wv[8] = { wa.x, wa.y, wa.z, wa.w, wb.x, wb.y, wb.z, wb.w };
            float vv[8] = { va.x, va.y, va.z, va.w, vb.x, vb.y, vb.z, vb.w };
#pragma unroll
            for (int i = 0; i < 8; i++)
#pragma unroll
                for (int j = 0; j < 8; j++)
                    acc[i][j] = fmaf(wv[i], vv[j], acc[i][j]);
        }
        __syncthreads();
    }

    float* pb = part + ((size_t)(b * GSPLIT + blockIdx.y) * 64) * HWSZ;
#pragma unroll
    for (int i = 0; i < 8; i++) {
        float* op = pb + (size_t)(oc0 + i) * HWSZ + p0 + px0;
        *(float4*)op       = make_float4(acc[i][0], acc[i][1], acc[i][2], acc[i][3]);
        *(float4*)(op + 4) = make_float4(acc[i][4], acc[i][5], acc[i][6], acc[i][7]);
    }
}

// ---------------- partial reduction ----------------
__global__ void reduce_kernel(const float4* __restrict__ part, float4* __restrict__ out) {
    int idx = blockIdx.x * 256 + threadIdx.x;
    if (idx >= 2 * 64 * HWSZ / 4) return;
    int b = idx / (64 * HWSZ / 4);
    int r = idx - b * (64 * HWSZ / 4);
    const float4* pp = part + (size_t)b * GSPLIT * (64 * HWSZ / 4) + r;
    float4 s = pp[0];
#pragma unroll
    for (int k = 1; k < GSPLIT; k++) {
        float4 v = pp[(size_t)k * (64 * HWSZ / 4)];
        s.x += v.x; s.y += v.y; s.z += v.z; s.w += v.w;
    }
    out[idx] = s;
}

// ---------------- launch ----------------
extern "C" void kernel_launch(void* const* d_in, const int* in_sizes, int n_in,
                              void* d_out, int out_size) {
    const float* x          = (const float*)d_in[0];
    const float* extra_feat = (const float*)d_in[1];
    const float* flow       = (const float*)d_in[2];
    const float* w1         = (const float*)d_in[3];
    const float* b1         = (const float*)d_in[4];
    const float* w2         = (const float*)d_in[5];
    const float* b2         = (const float*)d_in[6];
    const float* w3         = (const float*)d_in[7];
    const float* b3         = (const float*)d_in[8];
    const float* weight     = (const float*)d_in[9];
    float* out = (float*)d_out;

    float *efp, *h1p, *h2, *obuf, *partb;
    float4* xt;
    cudaGetSymbolAddress((void**)&efp, g_efp);
    cudaGetSymbolAddress((void**)&h1p, g_h1p);
    cudaGetSymbolAddress((void**)&h2, g_h2);
    cudaGetSymbolAddress((void**)&obuf, g_o);
    cudaGetSymbolAddress((void**)&xt, g_xt);
    cudaGetSymbolAddress((void**)&partb, g_part);

    cudaFuncSetAttribute(conv_pad_kernel<true>,
                         cudaFuncAttributeMaxDynamicSharedMemorySize, SMEM_PAD);
    cudaFuncSetAttribute(conv_raw_kernel<false>,
                         cudaFuncAttributeMaxDynamicSharedMemorySize, SMEM_RAW);

    pad_kernel<<<(2 * 128 * HWSZ + 255) / 256, 256>>>(extra_feat, efp, 2 * 128 * HWSZ);
    transpose_x_kernel<<<(2 * 16 * HWSZ + 255) / 256, 256>>>(x, xt);

    // conv1: 128 -> 64, leaky, padded -> padded (variant A)
    conv_pad_kernel<true><<<dim3(16, 8, 2), 256, SMEM_PAD>>>(
        efp, w1, b1, h1p, 128, 64, PW, PW + 4, (size_t)PHW);
    // conv2: 64 -> 64, leaky, padded -> raw (variant A)
    conv_pad_kernel<true><<<dim3(16, 8, 2), 256, SMEM_PAD>>>(
        h1p, w2, b2, h2, 64, 64, WW, 0, (size_t)HWSZ);
    // conv3: 64 -> 432, linear, raw -> raw (variant B, 3 CTA/SM)
    conv_raw_kernel<false><<<dim3(16, 54, 2), 256, SMEM_RAW>>>(
        h2, w3, b3, obuf, 64, 432);

    deform_kernel<<<dim3(HWSZ / 128, GSPLIT, 2), 128>>>(xt, obuf, flow, weight, partb);
    reduce_kernel<<<(2 * 64 * HWSZ / 4 + 255) / 256, 256>>>((const float4*)partb, (float4*)out);
}

// round 16
// speedup vs baseline: 1.0783x; 1.0701x over previous
#include <cuda_runtime.h>
#include <cstdint>

#define HH 128
#define WW 128
#define HWSZ (HH * WW)

// padded geometry: 130 rows x 136 cols; interior pixel (y,x) at (y+1)*136 + (x+4).
#define PW 136
#define PH 130
#define PHW (PH * PW)

#define GSPLIT 8   // deform group-split factor (16 groups / 2 per block)

// ---------------- scratch (zero-initialized device globals; halo ring never written) ----
__device__ float  g_efp[2 * 128 * PHW];
__device__ float  g_h1p[2 * 64 * PHW];
__device__ float  g_h2p[2 * 64 * PHW];
__device__ float  g_o  [2 * 432 * HWSZ];
__device__ float4 g_xt [2 * 16 * HWSZ];
__device__ float  g_part[2 * GSPLIT * 64 * HWSZ];   // deform partial sums

// ---------------- cp.async helpers ----------------
__device__ __forceinline__ unsigned su32(const void* p) {
    return (unsigned)__cvta_generic_to_shared(p);
}
__device__ __forceinline__ void cpa16(unsigned d, const void* s) {
    asm volatile("cp.async.ca.shared.global [%0], [%1], 16;" :: "r"(d), "l"(s));
}
__device__ __forceinline__ void cpa4(unsigned d, const void* s) {
    asm volatile("cp.async.ca.shared.global [%0], [%1], 4;" :: "r"(d), "l"(s));
}
__device__ __forceinline__ void cpcommit() { asm volatile("cp.async.commit_group;"); }
__device__ __forceinline__ void cpwait0()  { asm volatile("cp.async.wait_group 0;"); }
__device__ __forceinline__ void cpwait1()  { asm volatile("cp.async.wait_group 1;"); }

// ---------------- pad copy: [BC,128,128] -> padded [BC,130,136] interior ----------------
__global__ void pad_kernel(const float* __restrict__ in, float* __restrict__ outp, int n) {
    int idx = blockIdx.x * 256 + threadIdx.x;
    if (idx >= n) return;
    int p = idx & (HWSZ - 1);
    int bc = idx >> 14;
    int y = p >> 7;
    int x = p & 127;
    outp[(size_t)bc * PHW + (y + 1) * PW + x + 4] = in[idx];
}

// ---------------- conv 3x3 fp32, cp.async double-buffered staging (R10/R11 winner) ------
constexpr int SIN_BUF = 8 * 34 * 40;
constexpr int SW_BUF  = 8 * 8 * 9;
constexpr int SMEM_CONV = (2 * SIN_BUF + 2 * SW_BUF) * 4;

template <bool LEAKY>
__global__ __launch_bounds__(256, 2)
void conv3x3_kernel(const float* __restrict__ in,
                    const float* __restrict__ wgt,
                    const float* __restrict__ bias,
                    float* __restrict__ out,
                    int Cin, int Cout, int OS, int OB, size_t ocs) {
    extern __shared__ float smem[];
    float* s_in = smem;
    float* s_w  = smem + 2 * SIN_BUF;

    const int tid = threadIdx.x;
    const int tx = tid & 15;
    const int ty = tid >> 4;
    const int tile = blockIdx.x;
    const int y0 = (tile >> 2) * 32;
    const int x0 = (tile & 3) * 32;
    const int ocb = blockIdx.y;
    const int b = blockIdx.z;

    const float* in_b = in + (size_t)b * Cin * PHW;
    const int s_ch = tid >> 5;
    const int s_ln = tid & 31;

    float acc[8][4];
#pragma unroll
    for (int i = 0; i < 8; i++) {
        acc[i][0] = 0.f; acc[i][1] = 0.f; acc[i][2] = 0.f; acc[i][3] = 0.f;
    }

    auto stage = [&](int c0, int bufi) {
        const float* src = in_b + (size_t)(c0 + s_ch) * PHW + y0 * PW + x0;
        float* dst = s_in + (size_t)(bufi * 8 + s_ch) * (34 * 40);
        for (int idx = s_ln; idx < 340; idx += 32) {
            int r = idx / 10;
            int q = idx - r * 10;
            cpa16(su32(dst + r * 40 + q * 4), src + r * PW + q * 4);
        }
        for (int idx = tid; idx < 576; idx += 256) {
            int oc = idx / 72;
            int rem = idx - oc * 72;
            int ci = rem / 9;
            int k = rem - ci * 9;
            cpa4(su32(s_w + bufi * SW_BUF + (oc * 8 + ci) * 9 + k),
                 wgt + ((size_t)(ocb * 8 + oc) * Cin + c0 + ci) * 9 + k);
        }
    };

    stage(0, 0);
    cpcommit();

    int buf = 0;
    for (int c0 = 0; c0 < Cin; c0 += 8) {
        if (c0 + 8 < Cin) {
            stage(c0 + 8, buf ^ 1);
            cpcommit();
            cpwait1();
        } else {
            cpwait0();
        }
        __syncthreads();

        const float* si = s_in + buf * SIN_BUF;
        const float* sw = s_w + buf * SW_BUF;
#pragma unroll
        for (int ci = 0; ci < 8; ci++) {
            const float* sc = si + ci * (34 * 40);
            float iv[4][4];
#pragma unroll
            for (int dy = 0; dy < 4; dy++)
#pragma unroll
                for (int dx = 0; dx < 4; dx++)
                    iv[dy][dx] = sc[(2 * ty + dy) * 40 + 2 * tx + dx + 3];
#pragma unroll
            for (int oc = 0; oc < 8; oc++) {
#pragma unroll
                for (int ky = 0; ky < 3; ky++)
#pragma unroll
                    for (int kx = 0; kx < 3; kx++) {
                        float w = sw[(oc * 8 + ci) * 9 + ky * 3 + kx];
                        acc[oc][0] = fmaf(iv[ky][kx],         w, acc[oc][0]);
                        acc[oc][1] = fmaf(iv[ky][kx + 1],     w, acc[oc][1]);
                        acc[oc][2] = fmaf(iv[ky + 1][kx],     w, acc[oc][2]);
                        acc[oc][3] = fmaf(iv[ky + 1][kx + 1], w, acc[oc][3]);
                    }
            }
        }
        __syncthreads();
        buf ^= 1;
    }

    const int oy = y0 + 2 * ty;
    const int ox = x0 + 2 * tx;
#pragma unroll
    for (int oc = 0; oc < 8; oc++) {
        float bv = bias[ocb * 8 + oc];
        float* op = out + (size_t)(b * Cout + ocb * 8 + oc) * ocs + OB;
#pragma unroll
        for (int q = 0; q < 4; q++) {
            float v = acc[oc][q] + bv;
            if (LEAKY) v = (v >= 0.f) ? v : 0.1f * v;
            int yy = oy + (q >> 1);
            int xx = ox + (q & 1);
            op[yy * OS + xx] = v;
        }
    }
}

// ---------------- x transpose: [B,64,H,W] -> [B,16,H,W,4] ----------------
__global__ void transpose_x_kernel(const float* __restrict__ x, float4* __restrict__ xt) {
    int idx = blockIdx.x * 256 + threadIdx.x;
    if (idx >= 2 * 16 * HWSZ) return;
    int p = idx & (HWSZ - 1);
    int bg = idx / HWSZ;
    const float* src = x + (size_t)bg * 4 * HWSZ + p;
    float4 v;
    v.x = src[0];
    v.y = src[HWSZ];
    v.z = src[2 * HWSZ];
    v.w = src[3 * HWSZ];
    xt[idx] = v;
}

// ---------------- deformable gather + block GEMM, group-split partials ----------------
__global__ __launch_bounds__(128, 4)
void deform_kernel(const float4* __restrict__ xt,
                   const float* __restrict__ o,
                   const float* __restrict__ flow,
                   const float* __restrict__ weight,   // [64][576]
                   float* __restrict__ part) {
    __shared__ __align__(16) float s_w[36 * 64];
    __shared__ __align__(16) float s_val[36 * 128];

    const int tid = threadIdx.x;
    const int b = blockIdx.z;
    const int gbase = blockIdx.y * (16 / GSPLIT);
    const int p0 = blockIdx.x * 128;
    const int p = p0 + tid;
    const int h = p >> 7;
    const int w = p & 127;
    const int px0 = (tid & 15) * 8;
    const int oc0 = (tid >> 4) * 8;

    const float* ob = o + (size_t)b * 432 * HWSZ + p;
    const float fy = flow[((size_t)b * 2 + 1) * HWSZ + p];
    const float fx = flow[((size_t)b * 2 + 0) * HWSZ + p];

    float acc[8][8];
#pragma unroll
    for (int i = 0; i < 8; i++)
#pragma unroll
        for (int j = 0; j < 8; j++) acc[i][j] = 0.f;

    for (int gi = 0; gi < 16 / GSPLIT; gi++) {
        const int g = gbase + gi;
        for (int idx = tid; idx < 36 * 64; idx += 128) {
            int m = idx >> 6;
            int oo = idx & 63;
            cpa4(su32(s_w + idx), weight + (size_t)oo * 576 + g * 36 + m);
        }
        cpcommit();

        const float4* xg = xt + (size_t)(b * 16 + g) * HWSZ;
#pragma unroll
        for (int k = 0; k < 9; k++) {
            float lo_y = ob[(size_t)(g * 18 + 2 * k) * HWSZ];
            float lo_x = ob[(size_t)(g * 18 + 2 * k + 1) * HWSZ];
            float lo_m = ob[(size_t)(288 + g * 9 + k) * HWSZ];

            float offy = 10.f * tanhf(lo_y) + fy;
            float offx = 10.f * tanhf(lo_x) + fx;
            float msk = 1.f / (1.f + expf(-lo_m));

            float py = (float)(h + (k / 3) - 1) + offy;
            float px = (float)(w + (k % 3) - 1) + offx;

            float y0f = floorf(py);
            float x0f = floorf(px);
            float wy = py - y0f;
            float wx = px - x0f;
            int y0 = (int)y0f;
            int x0 = (int)x0f;

            bool y0v = ((unsigned)y0 < HH);
            bool y1v = ((unsigned)(y0 + 1) < HH);
            bool x0v = ((unsigned)x0 < WW);
            bool x1v = ((unsigned)(x0 + 1) < WW);

            float4 v00 = make_float4(0.f, 0.f, 0.f, 0.f);
            float4 v01 = v00, v10 = v00, v11 = v00;
            if (y0v && x0v) v00 = __ldg(&xg[y0 * WW + x0]);
            if (y0v && x1v) v01 = __ldg(&xg[y0 * WW + x0 + 1]);
            if (y1v && x0v) v10 = __ldg(&xg[(y0 + 1) * WW + x0]);
            if (y1v && x1v) v11 = __ldg(&xg[(y0 + 1) * WW + x0 + 1]);

            float w00 = (1.f - wy) * (1.f - wx);
            float w01 = (1.f - wy) * wx;
            float w10 = wy * (1.f - wx);
            float w11 = wy * wx;

            s_val[(0 * 9 + k) * 128 + tid] = msk * (w00 * v00.x + w01 * v01.x + w10 * v10.x + w11 * v11.x);
            s_val[(1 * 9 + k) * 128 + tid] = msk * (w00 * v00.y + w01 * v01.y + w10 * v10.y + w11 * v11.y);
            s_val[(2 * 9 + k) * 128 + tid] = msk * (w00 * v00.z + w01 * v01.z + w10 * v10.z + w11 * v11.z);
            s_val[(3 * 9 + k) * 128 + tid] = msk * (w00 * v00.w + w01 * v01.w + w10 * v10.w + w11 * v11.w);
        }

        cpwait0();
        __syncthreads();

#pragma unroll
        for (int m = 0; m < 36; m++) {
            float4 wa = *(const float4*)(s_w + m * 64 + oc0);
            float4 wb = *(const float4*)(s_w + m * 64 + oc0 + 4);
            float4 va = *(const float4*)(s_val + m * 128 + px0);
            float4 vb = *(const float4*)(s_val + m * 128 + px0 + 4);
            float wv[8] = { wa.x, wa.y, wa.z, wa.w, wb.x, wb.y, wb.z, wb.w };
            float vv[8] = { va.x, va.y, va.z, va.w, vb.x, vb.y, vb.z, vb.w };
#pragma unroll
            for (int i = 0; i < 8; i++)
#pragma unroll
                for (int j = 0; j < 8; j++)
                    acc[i][j] = fmaf(wv[i], vv[j], acc[i][j]);
        }
        __syncthreads();
    }

    float* pb = part + ((size_t)(b * GSPLIT + blockIdx.y) * 64) * HWSZ;
#pragma unroll
    for (int i = 0; i < 8; i++) {
        float* op = pb + (size_t)(oc0 + i) * HWSZ + p0 + px0;
        *(float4*)op       = make_float4(acc[i][0], acc[i][1], acc[i][2], acc[i][3]);
        *(float4*)(op + 4) = make_float4(acc[i][4], acc[i][5], acc[i][6], acc[i][7]);
    }
}

// ---------------- partial reduction ----------------
__global__ void reduce_kernel(const float4* __restrict__ part, float4* __restrict__ out) {
    int idx = blockIdx.x * 256 + threadIdx.x;
    if (idx >= 2 * 64 * HWSZ / 4) return;
    int b = idx / (64 * HWSZ / 4);
    int r = idx - b * (64 * HWSZ / 4);
    const float4* pp = part + (size_t)b * GSPLIT * (64 * HWSZ / 4) + r;
    float4 s = pp[0];
#pragma unroll
    for (int k = 1; k < GSPLIT; k++) {
        float4 v = pp[(size_t)k * (64 * HWSZ / 4)];
        s.x += v.x; s.y += v.y; s.z += v.z; s.w += v.w;
    }
    out[idx] = s;
}

// ---------------- launch ----------------
extern "C" void kernel_launch(void* const* d_in, const int* in_sizes, int n_in,
                              void* d_out, int out_size) {
    const float* x          = (const float*)d_in[0];
    const float* extra_feat = (const float*)d_in[1];
    const float* flow       = (const float*)d_in[2];
    const float* w1         = (const float*)d_in[3];
    const float* b1         = (const float*)d_in[4];
    const float* w2         = (const float*)d_in[5];
    const float* b2         = (const float*)d_in[6];
    const float* w3         = (const float*)d_in[7];
    const float* b3         = (const float*)d_in[8];
    const float* weight     = (const float*)d_in[9];
    float* out = (float*)d_out;

    float *efp, *h1p, *h2p, *obuf, *partb;
    float4* xt;
    cudaGetSymbolAddress((void**)&efp, g_efp);
    cudaGetSymbolAddress((void**)&h1p, g_h1p);
    cudaGetSymbolAddress((void**)&h2p, g_h2p);
    cudaGetSymbolAddress((void**)&obuf, g_o);
    cudaGetSymbolAddress((void**)&xt, g_xt);
    cudaGetSymbolAddress((void**)&partb, g_part);

    cudaFuncSetAttribute(conv3x3_kernel<true>,
                         cudaFuncAttributeMaxDynamicSharedMemorySize, SMEM_CONV);
    cudaFuncSetAttribute(conv3x3_kernel<false>,
                         cudaFuncAttributeMaxDynamicSharedMemorySize, SMEM_CONV);

    pad_kernel<<<(2 * 128 * HWSZ + 255) / 256, 256>>>(extra_feat, efp, 2 * 128 * HWSZ);
    transpose_x_kernel<<<(2 * 16 * HWSZ + 255) / 256, 256>>>(x, xt);

    conv3x3_kernel<true><<<dim3(16, 8, 2), 256, SMEM_CONV>>>(
        efp, w1, b1, h1p, 128, 64, PW, PW + 4, (size_t)PHW);
    conv3x3_kernel<true><<<dim3(16, 8, 2), 256, SMEM_CONV>>>(
        h1p, w2, b2, h2p, 64, 64, PW, PW + 4, (size_t)PHW);
    conv3x3_kernel<false><<<dim3(16, 54, 2), 256, SMEM_CONV>>>(
        h2p, w3, b3, obuf, 64, 432, WW, 0, (size_t)HWSZ);

    deform_kernel<<<dim3(HWSZ / 128, GSPLIT, 2), 128>>>(xt, obuf, flow, weight, partb);
    reduce_kernel<<<(2 * 64 * HWSZ / 4 + 255) / 256, 256>>>((const float4*)partb, (float4*)out);
}